// round 4
// baseline (speedup 1.0000x reference)
#include <cuda_runtime.h>

// Problem constants (fixed by the reference setup_inputs)
#define BB      4
#define CC      96
#define HH      192
#define WW      320
#define HW      (HH * WW)          // 61440
#define HW4     (HW / 4)           // 15360 float4 per (b, plane)
#define OUT_CH  81

#define PIXB    32                 // float4-pixels per block (threadIdx.x)
#define CSPLIT  8                  // channel splits per pixel (threadIdx.y)
#define CPER    (CC / CSPLIT)      // 12 channels per thread

// Scratch: corr volume [B, HW4] float4 = 983 KB. Static device alloc (allowed).
__device__ float4 g_corr[BB * HW4];

// ---------------------------------------------------------------------------
// K1: read-dominant. corr[b,p] = (sum_c f1*f2) * mask / C.
// Reads 188.7 MB (streaming), writes 0.98 MB (write-back -> stays in L2).
// ---------------------------------------------------------------------------
__global__ __launch_bounds__(PIXB * CSPLIT) void corr_kernel(
    const float4* __restrict__ f1,
    const float4* __restrict__ f2)
{
    __shared__ float4 s_dot[CSPLIT][PIXB];
    __shared__ float4 s_abs[CSPLIT][PIXB];

    const int x = threadIdx.x;
    const int y = threadIdx.y;
    const int px = blockIdx.x * PIXB + x;      // [0, BB*HW4)

    const int b = px / HW4;                    // uniform per block
    const int p = px - b * HW4;

    const size_t base = (size_t)b * CC * HW4 + (size_t)(y * CPER) * HW4 + p;
    const float4* __restrict__ f1p = f1 + base;
    const float4* __restrict__ f2p = f2 + base;

    float dx = 0.f, dy = 0.f, dz = 0.f, dw = 0.f;
    float ax = 0.f, ay = 0.f, az = 0.f, aw = 0.f;

#pragma unroll
    for (int c = 0; c < CPER; ++c) {
        float4 a = __ldcs(f1p + (size_t)c * HW4);
        float4 v = __ldcs(f2p + (size_t)c * HW4);
        dx = fmaf(a.x, v.x, dx);
        dy = fmaf(a.y, v.y, dy);
        dz = fmaf(a.z, v.z, dz);
        dw = fmaf(a.w, v.w, dw);
        ax += fabsf(a.x);
        ay += fabsf(a.y);
        az += fabsf(a.z);
        aw += fabsf(a.w);
    }

    s_dot[y][x] = make_float4(dx, dy, dz, dw);
    s_abs[y][x] = make_float4(ax, ay, az, aw);
    __syncthreads();

    if (y == 0) {
        float fdx = 0.f, fdy = 0.f, fdz = 0.f, fdw = 0.f;
        float fax = 0.f, fay = 0.f, faz = 0.f, faw = 0.f;
#pragma unroll
        for (int k = 0; k < CSPLIT; ++k) {
            float4 d = s_dot[k][x];
            float4 a = s_abs[k][x];
            fdx += d.x; fdy += d.y; fdz += d.z; fdw += d.w;
            fax += a.x; fay += a.y; faz += a.z; faw += a.w;
        }
        const float inv_c = 1.0f / (float)CC;
        float4 r;
        r.x = (fax > 0.1f) ? fdx * inv_c : 0.0f;
        r.y = (fay > 0.1f) ? fdy * inv_c : 0.0f;
        r.z = (faz > 0.1f) ? fdz * inv_c : 0.0f;
        r.w = (faw > 0.1f) ? fdw * inv_c : 0.0f;
        g_corr[px] = r;   // write-back: stays resident in L2 for K2
    }
}

// ---------------------------------------------------------------------------
// K2: write-dominant broadcast. out[b,oc,p] = corr[b,p] for all 81 oc.
// Reads 983 KB working set (L2 hits), streams 79.6 MB of writes.
// grid: (HW4/256, OUT_CH*BB)
// ---------------------------------------------------------------------------
__global__ __launch_bounds__(256) void bcast_kernel(float4* __restrict__ out)
{
    const int p = blockIdx.x * 256 + threadIdx.x;   // [0, HW4)
    const int plane = blockIdx.y;                   // [0, OUT_CH*BB)
    const int b = plane / OUT_CH;                   // uniform per block

    float4 r = __ldg(&g_corr[b * HW4 + p]);         // L2-resident
    __stcs(out + (size_t)plane * HW4 + p, r);
}

extern "C" void kernel_launch(void* const* d_in, const int* in_sizes, int n_in,
                              void* d_out, int out_size)
{
    const float4* f1 = (const float4*)d_in[0];
    const float4* f2 = (const float4*)d_in[1];
    float4* out = (float4*)d_out;

    dim3 block1(PIXB, CSPLIT);                     // 256 threads
    dim3 grid1((BB * HW4) / PIXB);                 // 1920 blocks
    corr_kernel<<<grid1, block1>>>(f1, f2);

    dim3 block2(256);
    dim3 grid2(HW4 / 256, OUT_CH * BB);            // 60 x 324
    bcast_kernel<<<grid2, block2>>>(out);
}

// round 8
// speedup vs baseline: 1.0461x; 1.0461x over previous
#include <cuda_runtime.h>
#include <cstdint>

// Problem constants (fixed by the reference setup_inputs)
#define BB      4
#define CC      96
#define HH      192
#define WW      320
#define HW      (HH * WW)          // 61440
#define HW4     (HW / 4)           // 15360 float4 per (b, plane)
#define OUT_CH  81

#define PIXB    32                 // float4-pixels per block (threadIdx.x)
#define CSPLIT  8                  // channel splits per pixel (threadIdx.y)
#define CPER    (CC / CSPLIT)      // 12 channels per thread

// Streaming read: L1 non-coherent, L2 evict-first via cache-hint policy
__device__ __forceinline__ float4 ldg_stream(const float4* p, uint64_t pol) {
    float4 v;
    asm volatile("ld.global.nc.L2::cache_hint.v4.f32 {%0,%1,%2,%3}, [%4], %5;"
                 : "=f"(v.x), "=f"(v.y), "=f"(v.z), "=f"(v.w)
                 : "l"(p), "l"(pol));
    return v;
}

// Resident write: L2 evict-last via cache-hint policy (output fits in L2)
__device__ __forceinline__ void stg_resident(float4* p, float4 v, uint64_t pol) {
    asm volatile("st.global.L2::cache_hint.v4.f32 [%0], {%1,%2,%3,%4}, %5;"
                 :: "l"(p), "f"(v.x), "f"(v.y), "f"(v.z), "f"(v.w), "l"(pol)
                 : "memory");
}

// corr[b,h,w] = (sum_c f1*f2) * mask / C ; mask = (sum_c |f1| > 0.1)
// out[b,oc,h,w] = corr[b,h,w] for all 81 oc.
__global__ __launch_bounds__(PIXB * CSPLIT) void spike_corr_kernel(
    const float4* __restrict__ f1,
    const float4* __restrict__ f2,
    float4* __restrict__ out)
{
    __shared__ float4 s_dot[CSPLIT][PIXB];
    __shared__ float4 s_abs[CSPLIT][PIXB];

    const int x = threadIdx.x;                 // pixel slot within block
    const int y = threadIdx.y;                 // channel slice
    const int px = blockIdx.x * PIXB + x;      // global float4-pixel [0, BB*HW4)

    const int b = px / HW4;                    // HW4 % PIXB == 0 -> uniform per block
    const int p = px - b * HW4;

    // L2 policies: evict_first for the streaming reads, evict_last for output
    uint64_t pol_rd, pol_wr;
    asm volatile("createpolicy.fractional.L2::evict_first.b64 %0, 1.0;" : "=l"(pol_rd));
    asm volatile("createpolicy.fractional.L2::evict_last.b64 %0, 1.0;"  : "=l"(pol_wr));

    const size_t base = (size_t)b * CC * HW4 + (size_t)(y * CPER) * HW4 + p;
    const float4* __restrict__ f1p = f1 + base;
    const float4* __restrict__ f2p = f2 + base;

    float dx = 0.f, dy = 0.f, dz = 0.f, dw = 0.f;
    float ax = 0.f, ay = 0.f, az = 0.f, aw = 0.f;

#pragma unroll
    for (int c = 0; c < CPER; ++c) {
        float4 a = ldg_stream(f1p + (size_t)c * HW4, pol_rd);
        float4 v = ldg_stream(f2p + (size_t)c * HW4, pol_rd);
        dx = fmaf(a.x, v.x, dx);
        dy = fmaf(a.y, v.y, dy);
        dz = fmaf(a.z, v.z, dz);
        dw = fmaf(a.w, v.w, dw);
        ax += fabsf(a.x);
        ay += fabsf(a.y);
        az += fabsf(a.z);
        aw += fabsf(a.w);
    }

    s_dot[y][x] = make_float4(dx, dy, dz, dw);
    s_abs[y][x] = make_float4(ax, ay, az, aw);
    __syncthreads();

    // Every thread (all 8 y's) redundantly reduces its pixel's 8 partials,
    // so each y can independently store its share of the 81 output channels.
    float fdx = 0.f, fdy = 0.f, fdz = 0.f, fdw = 0.f;
    float fax = 0.f, fay = 0.f, faz = 0.f, faw = 0.f;
#pragma unroll
    for (int k = 0; k < CSPLIT; ++k) {
        float4 d = s_dot[k][x];
        float4 a = s_abs[k][x];
        fdx += d.x; fdy += d.y; fdz += d.z; fdw += d.w;
        fax += a.x; fay += a.y; faz += a.z; faw += a.w;
    }

    const float inv_c = 1.0f / (float)CC;
    float4 r;
    r.x = (fax > 0.1f) ? fdx * inv_c : 0.0f;
    r.y = (fay > 0.1f) ? fdy * inv_c : 0.0f;
    r.z = (faz > 0.1f) ? fdz * inv_c : 0.0f;
    r.w = (faw > 0.1f) ? fdw * inv_c : 0.0f;

    float4* __restrict__ op = out + (size_t)b * OUT_CH * HW4 + p;
    // y-th thread stores channels y, y+8, y+16, ... (10-11 stores each)
#pragma unroll
    for (int oc = y; oc < OUT_CH; oc += CSPLIT) {
        stg_resident(op + (size_t)oc * HW4, r, pol_wr);
    }
}

extern "C" void kernel_launch(void* const* d_in, const int* in_sizes, int n_in,
                              void* d_out, int out_size)
{
    const float4* f1 = (const float4*)d_in[0];
    const float4* f2 = (const float4*)d_in[1];
    float4* out = (float4*)d_out;

    dim3 block(PIXB, CSPLIT);                  // 256 threads
    dim3 grid((BB * HW4) / PIXB);              // 1920 blocks
    spike_corr_kernel<<<grid, block>>>(f1, f2, out);
}

// round 11
// speedup vs baseline: 1.1799x; 1.1279x over previous
#include <cuda_runtime.h>
#include <cstdint>

// Problem constants (fixed by the reference setup_inputs)
#define BB      4
#define CC      96
#define HH      192
#define WW      320
#define HW      (HH * WW)          // 61440
#define HW4     (HW / 4)           // 15360 float4 per (b, plane)
#define OUT_CH  81

#define PIXB    32                 // float4-pixels per block (threadIdx.x)
#define CSPLIT  8                  // channel splits per pixel (threadIdx.y)
#define CPER    (CC / CSPLIT)      // 12 channels per thread
#define BATCH   6                  // channels per load batch -> 12 LDG.128 in flight

// Streaming read: L1 non-coherent, L2 evict-first via cache-hint policy
__device__ __forceinline__ float4 ldg_stream(const float4* p, uint64_t pol) {
    float4 v;
    asm volatile("ld.global.nc.L2::cache_hint.v4.f32 {%0,%1,%2,%3}, [%4], %5;"
                 : "=f"(v.x), "=f"(v.y), "=f"(v.z), "=f"(v.w)
                 : "l"(p), "l"(pol));
    return v;
}

// Resident write: L2 evict-last via cache-hint policy (output fits in L2)
__device__ __forceinline__ void stg_resident(float4* p, float4 v, uint64_t pol) {
    asm volatile("st.global.L2::cache_hint.v4.f32 [%0], {%1,%2,%3,%4}, %5;"
                 :: "l"(p), "f"(v.x), "f"(v.y), "f"(v.z), "f"(v.w), "l"(pol)
                 : "memory");
}

// corr[b,h,w] = (sum_c f1*f2) * mask / C ; mask = (sum_c |f1| > 0.1)
// out[b,oc,h,w] = corr[b,h,w] for all 81 oc.
__global__ __launch_bounds__(PIXB * CSPLIT, 3) void spike_corr_kernel(
    const float4* __restrict__ f1,
    const float4* __restrict__ f2,
    float4* __restrict__ out)
{
    __shared__ float4 s_dot[CSPLIT][PIXB];
    __shared__ float4 s_abs[CSPLIT][PIXB];

    const int x = threadIdx.x;                 // pixel slot within block
    const int y = threadIdx.y;                 // channel slice
    const int px = blockIdx.x * PIXB + x;      // global float4-pixel [0, BB*HW4)

    const int b = px / HW4;                    // HW4 % PIXB == 0 -> uniform per block
    const int p = px - b * HW4;

    // L2 policies: evict_first for the streaming reads, evict_last for output
    uint64_t pol_rd, pol_wr;
    asm volatile("createpolicy.fractional.L2::evict_first.b64 %0, 1.0;" : "=l"(pol_rd));
    asm volatile("createpolicy.fractional.L2::evict_last.b64 %0, 1.0;"  : "=l"(pol_wr));

    const size_t base = (size_t)b * CC * HW4 + (size_t)(y * CPER) * HW4 + p;
    const float4* __restrict__ f1p = f1 + base;
    const float4* __restrict__ f2p = f2 + base;

    float dx = 0.f, dy = 0.f, dz = 0.f, dw = 0.f;
    float ax = 0.f, ay = 0.f, az = 0.f, aw = 0.f;

    // Two batches of 6 channels; each batch issues 12 independent LDG.128
    // before any consumer -> MLP_eff ~ 12 per thread.
#pragma unroll
    for (int t = 0; t < CPER; t += BATCH) {
        float4 a[BATCH], v[BATCH];
#pragma unroll
        for (int j = 0; j < BATCH; ++j)
            a[j] = ldg_stream(f1p + (size_t)(t + j) * HW4, pol_rd);
#pragma unroll
        for (int j = 0; j < BATCH; ++j)
            v[j] = ldg_stream(f2p + (size_t)(t + j) * HW4, pol_rd);
#pragma unroll
        for (int j = 0; j < BATCH; ++j) {
            dx = fmaf(a[j].x, v[j].x, dx);
            dy = fmaf(a[j].y, v[j].y, dy);
            dz = fmaf(a[j].z, v[j].z, dz);
            dw = fmaf(a[j].w, v[j].w, dw);
            ax += fabsf(a[j].x);
            ay += fabsf(a[j].y);
            az += fabsf(a[j].z);
            aw += fabsf(a[j].w);
        }
    }

    s_dot[y][x] = make_float4(dx, dy, dz, dw);
    s_abs[y][x] = make_float4(ax, ay, az, aw);
    __syncthreads();

    // Every thread (all 8 y's) redundantly reduces its pixel's 8 partials,
    // so each y can independently store its share of the 81 output channels.
    float fdx = 0.f, fdy = 0.f, fdz = 0.f, fdw = 0.f;
    float fax = 0.f, fay = 0.f, faz = 0.f, faw = 0.f;
#pragma unroll
    for (int k = 0; k < CSPLIT; ++k) {
        float4 d = s_dot[k][x];
        float4 a = s_abs[k][x];
        fdx += d.x; fdy += d.y; fdz += d.z; fdw += d.w;
        fax += a.x; fay += a.y; faz += a.z; faw += a.w;
    }

    const float inv_c = 1.0f / (float)CC;
    float4 r;
    r.x = (fax > 0.1f) ? fdx * inv_c : 0.0f;
    r.y = (fay > 0.1f) ? fdy * inv_c : 0.0f;
    r.z = (faz > 0.1f) ? fdz * inv_c : 0.0f;
    r.w = (faw > 0.1f) ? fdw * inv_c : 0.0f;

    float4* __restrict__ op = out + (size_t)b * OUT_CH * HW4 + p;
    // y-th thread stores channels y, y+8, y+16, ... (10-11 stores each)
#pragma unroll
    for (int oc = y; oc < OUT_CH; oc += CSPLIT) {
        stg_resident(op + (size_t)oc * HW4, r, pol_wr);
    }
}

extern "C" void kernel_launch(void* const* d_in, const int* in_sizes, int n_in,
                              void* d_out, int out_size)
{
    const float4* f1 = (const float4*)d_in[0];
    const float4* f2 = (const float4*)d_in[1];
    float4* out = (float4*)d_out;

    dim3 block(PIXB, CSPLIT);                  // 256 threads
    dim3 grid((BB * HW4) / PIXB);              // 1920 blocks
    spike_corr_kernel<<<grid, block>>>(f1, f2, out);
}